// round 1
// baseline (speedup 1.0000x reference)
#include <cuda_runtime.h>
#include <math.h>

#define BB 64
#define TT 2048
#define FF 64
#define KK 512
#define DD 512
#define LN_EPS 1e-5f
#define G_MIN 0.05f
#define G_MAX 0.95f

// Scratch (allocation-free rule: __device__ globals)
__device__ __align__(16) float gM[DD * FF];    // M = W_w @ P_w        [D,F]
__device__ __align__(16) float gA[FF * FF];    // A = M'^T M' / D      [F,F] (symmetric)
__device__ __align__(16) float gU[FF];         // u = M^T c' / D       [F]
__device__ __align__(16) float gCp[DD];        // c' = (W_b+b) - mean  [D]
__device__ __align__(16) float gMbar[FF];      // column means of M    [F]
__device__ float gV[1];                        // v = |c'|^2 / D

// ---------------------------------------------------------------------------
// K1: M[d][f] = sum_k W_w[d][k] * P_w[k][f].  grid(D), block(F).
// ---------------------------------------------------------------------------
__global__ void k_computeM(const float* __restrict__ Ww, const float* __restrict__ Pw) {
    __shared__ float sW[KK];
    const int d = blockIdx.x;
    const int tid = threadIdx.x;  // 0..63 = f
    const float* wrow = Ww + (size_t)d * KK;
#pragma unroll
    for (int i = 0; i < KK / FF; i++) sW[i * FF + tid] = wrow[i * FF + tid];
    __syncthreads();
    float acc = 0.f;
#pragma unroll 8
    for (int k = 0; k < KK; k++) acc += sW[k] * Pw[k * FF + tid];
    gM[d * FF + tid] = acc;
}

// ---------------------------------------------------------------------------
// K2: grid(F+1), block(64).
//   blocks 0..F-1: row f1 of A (uses chunked shared tiles of M, single pass
//                  also produces column sums -> mbar), block 0 stores gMbar.
//   block F:       c', cbar, v, u.
// ---------------------------------------------------------------------------
__global__ void k_stats(const float* __restrict__ Wb, const float* __restrict__ bvec) {
    __shared__ float sChunk[64 * FF];  // 16 KB
    __shared__ float sCol[FF];
    __shared__ float sCp[DD];          // 2 KB
    const int tid = threadIdx.x;

    if (blockIdx.x < FF) {
        const int f1 = blockIdx.x;
        float accRaw = 0.f, accCol = 0.f;
        for (int c = 0; c < DD / 64; c++) {
#pragma unroll
            for (int r = 0; r < 64; r++)
                sChunk[r * FF + tid] = gM[(c * 64 + r) * FF + tid];
            __syncthreads();
#pragma unroll 8
            for (int r = 0; r < 64; r++) {
                float vt = sChunk[r * FF + tid];
                accRaw += sChunk[r * FF + f1] * vt;  // broadcast, conflict-free
                accCol += vt;
            }
            __syncthreads();
        }
        sCol[tid] = accCol;
        __syncthreads();
        const float m1 = sCol[f1] * (1.0f / DD);
        const float m2 = accCol * (1.0f / DD);
        // A[f1][f2] = raw/D - mbar[f1]*mbar[f2]
        gA[f1 * FF + tid] = accRaw * (1.0f / DD) - m1 * m2;
        if (f1 == 0) gMbar[tid] = m2;
    } else {
        // c = W_b + b ; c' = c - mean(c) ; v = |c'|^2/D ; u[f] = sum_d M[d][f]*c'[d] / D
        float cv[8];
        float ssum = 0.f;
#pragma unroll
        for (int i = 0; i < 8; i++) {
            cv[i] = Wb[i * 64 + tid] + bvec[i * 64 + tid];
            ssum += cv[i];
        }
        sCol[tid] = ssum;
        __syncthreads();
        for (int o = 32; o > 0; o >>= 1) {
            if (tid < o) sCol[tid] += sCol[tid + o];
            __syncthreads();
        }
        const float cbar = sCol[0] * (1.0f / DD);
        __syncthreads();
        float vsum = 0.f;
#pragma unroll
        for (int i = 0; i < 8; i++) {
            float cp = cv[i] - cbar;
            sCp[i * 64 + tid] = cp;
            gCp[i * 64 + tid] = cp;
            vsum += cp * cp;
        }
        sCol[tid] = vsum;
        __syncthreads();
        for (int o = 32; o > 0; o >>= 1) {
            if (tid < o) sCol[tid] += sCol[tid + o];
            __syncthreads();
        }
        if (tid == 0) gV[0] = sCol[0] * (1.0f / DD);
        float uacc = 0.f;
#pragma unroll 4
        for (int d0 = 0; d0 < DD; d0++) uacc += gM[d0 * FF + tid] * sCp[d0];
        gU[tid] = uacc * (1.0f / DD);
    }
}

// ---------------------------------------------------------------------------
// K3: per-batch truncated EMA over the last n steps + final GEMV.
//     grid(B), block(64). thread f owns Xtilde[f].
// ---------------------------------------------------------------------------
__global__ void k_main(const float* __restrict__ x,
                       const float* __restrict__ th1, const float* __restrict__ ph1,
                       const float* __restrict__ th2, const float* __restrict__ ph2,
                       const float* __restrict__ w1p, const float* __restrict__ w2p,
                       const float* __restrict__ bgp,
                       const float* __restrict__ gamma, const float* __restrict__ beta,
                       float* __restrict__ out) {
    __shared__ float sA[FF * FF];  // 16 KB
    __shared__ float sU[FF];
    __shared__ float sMb[FF];
    __shared__ float sx[FF];
    __shared__ float sred[2];
    const int tid = threadIdx.x;  // 0..63
    const int b = blockIdx.x;

#pragma unroll
    for (int i = 0; i < FF; i++) sA[i * FF + tid] = gA[i * FF + tid];
    sU[tid] = gU[tid];
    sMb[tid] = gMbar[tid];
    const float v = gV[0];

    // gate g (scalar, same for all threads)
    const float z1 = cosf(th1[0]) * cosf(ph1[0]);
    const float z2 = cosf(th2[0]) * cosf(ph2[0]);
    const float zg = w1p[0] * z1 + w2p[0] * z2 + bgp[0];
    float g = 1.0f / (1.0f + expf(-zg));
    g = fminf(fmaxf(g, G_MIN), G_MAX);
    const float omg = 1.0f - g;

    // truncation length: (1-g)^n <= 1e-10
    int n = (int)ceilf(-23.03f / logf(omg));
    if (n < 1) n = 1;
    if (n > TT) n = TT;

    float w = g;           // weight g*(1-g)^j
    float xacc = 0.f;      // Xtilde[tid]
    float Sacc = 0.f;      // sum of w*s (identical across threads)
    const float* xb = x + (size_t)b * TT * FF;
    __syncthreads();

    for (int j = 0; j < n; j++) {
        const int t = TT - 1 - j;
        const float xv = xb[t * FF + tid];
        sx[tid] = xv;
        __syncthreads();
        float acc = 0.f;
#pragma unroll
        for (int f2 = 0; f2 < FF; f2++) acc += sA[f2 * FF + tid] * sx[f2];  // A symmetric
        float p = xv * (acc + 2.0f * sU[tid]);
#pragma unroll
        for (int o = 16; o > 0; o >>= 1) p += __shfl_down_sync(0xffffffffu, p, o);
        if ((tid & 31) == 0) sred[tid >> 5] = p;
        __syncthreads();
        const float var = sred[0] + sred[1] + v;
        const float s = rsqrtf(var + LN_EPS);
        const float coef = w * s;
        xacc += coef * xv;
        Sacc += coef;
        w *= omg;
        __syncthreads();
    }

    sx[tid] = xacc;  // Xtilde now in shared
    __syncthreads();

    // total weight of ALL T steps: 1 - (1-g)^T
    const float Wsum = 1.0f - expf((float)TT * logf(omg));

    // h[b][d] = gamma[d]*( (M' Xtilde)[d] + c'[d]*S ) + beta[d]*Wsum
    float* ob = out + (size_t)b * DD;
    for (int k0 = 0; k0 < DD / 64; k0++) {
        const int d = k0 * 64 + tid;
        const float4* mrow = reinterpret_cast<const float4*>(gM + d * FF);
        float dot = 0.f;
#pragma unroll
        for (int q = 0; q < FF / 4; q++) {
            float4 m4 = mrow[q];
            dot += (m4.x - sMb[q * 4 + 0]) * sx[q * 4 + 0]
                 + (m4.y - sMb[q * 4 + 1]) * sx[q * 4 + 1]
                 + (m4.z - sMb[q * 4 + 2]) * sx[q * 4 + 2]
                 + (m4.w - sMb[q * 4 + 3]) * sx[q * 4 + 3];
        }
        ob[d] = gamma[d] * (dot + gCp[d] * Sacc) + beta[d] * Wsum;
    }
}

// ---------------------------------------------------------------------------
// Input order (metadata): x, theta1, phi1, theta2, phi2, w1, w2, b_g,
//                         P_w, W_w, W_b, b, ln_gamma, ln_beta, alpha
// alpha / cal_scalar cancel inside LayerNorm (uniform shift across D).
// ---------------------------------------------------------------------------
extern "C" void kernel_launch(void* const* d_in, const int* in_sizes, int n_in,
                              void* d_out, int out_size) {
    const float* x     = (const float*)d_in[0];
    const float* th1   = (const float*)d_in[1];
    const float* ph1   = (const float*)d_in[2];
    const float* th2   = (const float*)d_in[3];
    const float* ph2   = (const float*)d_in[4];
    const float* w1p   = (const float*)d_in[5];
    const float* w2p   = (const float*)d_in[6];
    const float* bgp   = (const float*)d_in[7];
    const float* Pw    = (const float*)d_in[8];
    const float* Ww    = (const float*)d_in[9];
    const float* Wb    = (const float*)d_in[10];
    const float* bvec  = (const float*)d_in[11];
    const float* gamma = (const float*)d_in[12];
    const float* beta  = (const float*)d_in[13];
    // d_in[14] = alpha: provably unused (LayerNorm shift invariance)

    k_computeM<<<DD, FF>>>(Ww, Pw);
    k_stats<<<FF + 1, 64>>>(Wb, bvec);
    k_main<<<BB, 64>>>(x, th1, ph1, th2, ph2, w1p, w2p, bgp, gamma, beta, (float*)d_out);
}

// round 2
// speedup vs baseline: 1.5213x; 1.5213x over previous
#include <cuda_runtime.h>
#include <math.h>

#define BB 64
#define TT 2048
#define FF 64
#define KK 512
#define DD 512
#define LN_EPS 1e-5f
#define G_MIN 0.05f
#define G_MAX 0.95f
#define NSL 8          // k-slices / d-slices

// Scratch (__device__ globals; no allocation allowed)
__device__ __align__(16) float gMpart[NSL * DD * FF];  // split-K partials of M   1MB
__device__ __align__(16) float gApart[NSL * FF * FF];  // split-D partials of raw A
__device__ __align__(16) float gMt[FF * DD];           // M transposed [f][d]
__device__ __align__(16) float gCp[DD];                // c' = (W_b+b) - mean
__device__ __align__(16) float gU[FF];                 // u = M^T c' / D
__device__ __align__(16) float gMbar[FF];              // column means of M
__device__ float gV[1];                                // |c'|^2 / D

// ---------------------------------------------------------------------------
// K1: blocks 0..63: split-K tiled GEMM  Mpart[ks][64d x 64f] = Wwtile @ Pwtile
//     block 64:     c' / cbar / v
//     256 threads.
// ---------------------------------------------------------------------------
__global__ void k1(const float* __restrict__ Ww, const float* __restrict__ Pw,
                   const float* __restrict__ Wb, const float* __restrict__ bvec) {
    __shared__ float sAt[64 * 65];   // Ww tile transposed: [k][d]
    __shared__ float sB[64 * 64];    // Pw tile: [k][f]
    const int tid = threadIdx.x;

    if (blockIdx.x < 64) {
        const int ct = blockIdx.x & 7;        // d tile
        const int ks = blockIdx.x >> 3;       // k slice
        const int d0 = ct * 64, k0 = ks * 64;

        // load Ww tile (transposed store) and Pw tile, float4 global reads
#pragma unroll
        for (int i = 0; i < 4; i++) {
            int idx4 = i * 256 + tid;         // 0..1023
            int kq = idx4 & 15, dy = idx4 >> 4;
            float4 w4 = *reinterpret_cast<const float4*>(Ww + (size_t)(d0 + dy) * KK + k0 + kq * 4);
            sAt[(kq * 4 + 0) * 65 + dy] = w4.x;
            sAt[(kq * 4 + 1) * 65 + dy] = w4.y;
            sAt[(kq * 4 + 2) * 65 + dy] = w4.z;
            sAt[(kq * 4 + 3) * 65 + dy] = w4.w;
            int fq = idx4 & 15, ky = idx4 >> 4;
            float4 p4 = *reinterpret_cast<const float4*>(Pw + (size_t)(k0 + ky) * FF + fq * 4);
            *reinterpret_cast<float4*>(sB + ky * 64 + fq * 4) = p4;
        }
        __syncthreads();

        const int tx = tid & 15, ty = tid >> 4;   // 16x16 thread tile, 4x4 micro
        float acc[4][4];
#pragma unroll
        for (int i = 0; i < 4; i++)
#pragma unroll
            for (int j = 0; j < 4; j++) acc[i][j] = 0.f;

#pragma unroll 4
        for (int k = 0; k < 64; k++) {
            float a0 = sAt[k * 65 + ty * 4 + 0];
            float a1 = sAt[k * 65 + ty * 4 + 1];
            float a2 = sAt[k * 65 + ty * 4 + 2];
            float a3 = sAt[k * 65 + ty * 4 + 3];
            float4 b4 = *reinterpret_cast<const float4*>(sB + k * 64 + tx * 4);
            acc[0][0] += a0 * b4.x; acc[0][1] += a0 * b4.y; acc[0][2] += a0 * b4.z; acc[0][3] += a0 * b4.w;
            acc[1][0] += a1 * b4.x; acc[1][1] += a1 * b4.y; acc[1][2] += a1 * b4.z; acc[1][3] += a1 * b4.w;
            acc[2][0] += a2 * b4.x; acc[2][1] += a2 * b4.y; acc[2][2] += a2 * b4.z; acc[2][3] += a2 * b4.w;
            acc[3][0] += a3 * b4.x; acc[3][1] += a3 * b4.y; acc[3][2] += a3 * b4.z; acc[3][3] += a3 * b4.w;
        }
        float* outp = gMpart + (size_t)ks * (DD * FF) + (size_t)(d0 + ty * 4) * FF + tx * 4;
#pragma unroll
        for (int i = 0; i < 4; i++) {
            float4 o4 = make_float4(acc[i][0], acc[i][1], acc[i][2], acc[i][3]);
            *reinterpret_cast<float4*>(outp + (size_t)i * FF) = o4;
        }
    } else {
        // c = W_b + b ; c' = c - mean(c) ; v = |c'|^2/D
        __shared__ float sred[64];
        float cv[8];
        float ssum = 0.f;
        if (tid < 64) {
#pragma unroll
            for (int i = 0; i < 8; i++) {
                cv[i] = Wb[i * 64 + tid] + bvec[i * 64 + tid];
                ssum += cv[i];
            }
            sred[tid] = ssum;
        }
        __syncthreads();
        for (int o = 32; o > 0; o >>= 1) {
            if (tid < o) sred[tid] += sred[tid + o];
            __syncthreads();
        }
        const float cbar = sred[0] * (1.0f / DD);
        __syncthreads();
        float vsum = 0.f;
        if (tid < 64) {
#pragma unroll
            for (int i = 0; i < 8; i++) {
                float cp = cv[i] - cbar;
                gCp[i * 64 + tid] = cp;
                vsum += cp * cp;
            }
            sred[tid] = vsum;
        }
        __syncthreads();
        for (int o = 32; o > 0; o >>= 1) {
            if (tid < o) sred[tid] += sred[tid + o];
            __syncthreads();
        }
        if (tid == 0) gV[0] = sred[0] * (1.0f / DD);
    }
}

// ---------------------------------------------------------------------------
// K2: blocks 0..7 (d-slice s): reduce Mpart slice -> sS, write gMt slice,
//     compute Apart[s] = sS^T sS (raw, uncentered).
//     block 8: u[f] and mbar[f] from partials + gCp.
//     256 threads.
// ---------------------------------------------------------------------------
__global__ void k2(int dummy) {
    const int tid = threadIdx.x;

    if (blockIdx.x < 8) {
        __shared__ float sS[64 * 68];   // reduced M slice [d][f], padded
        const int s = blockIdx.x;
        // reduce 8 partials for this slice
#pragma unroll
        for (int i = 0; i < 16; i++) {
            int e = i * 256 + tid;          // 0..4095
            int dl = e >> 6, f = e & 63;
            size_t off = (size_t)(s * 64 + dl) * FF + f;
            float acc = 0.f;
#pragma unroll
            for (int sl = 0; sl < NSL; sl++) acc += gMpart[(size_t)sl * (DD * FF) + off];
            sS[dl * 68 + f] = acc;
        }
        __syncthreads();
        // write M transposed: gMt[f*512 + s*64 + dl]
#pragma unroll
        for (int i = 0; i < 16; i++) {
            int e = i * 256 + tid;
            int f = e >> 6, dl = e & 63;
            gMt[(size_t)f * DD + s * 64 + dl] = sS[dl * 68 + f];
        }
        // Apart[s][f1][f2] = sum_d sS[d][f1]*sS[d][f2]
        const int tx = tid & 15, ty = tid >> 4;
        float acc[4][4];
#pragma unroll
        for (int i = 0; i < 4; i++)
#pragma unroll
            for (int j = 0; j < 4; j++) acc[i][j] = 0.f;
#pragma unroll 4
        for (int d = 0; d < 64; d++) {
            float4 a4 = *reinterpret_cast<const float4*>(sS + d * 68 + ty * 4);
            float4 b4 = *reinterpret_cast<const float4*>(sS + d * 68 + tx * 4);
            acc[0][0] += a4.x * b4.x; acc[0][1] += a4.x * b4.y; acc[0][2] += a4.x * b4.z; acc[0][3] += a4.x * b4.w;
            acc[1][0] += a4.y * b4.x; acc[1][1] += a4.y * b4.y; acc[1][2] += a4.y * b4.z; acc[1][3] += a4.y * b4.w;
            acc[2][0] += a4.z * b4.x; acc[2][1] += a4.z * b4.y; acc[2][2] += a4.z * b4.z; acc[2][3] += a4.z * b4.w;
            acc[3][0] += a4.w * b4.x; acc[3][1] += a4.w * b4.y; acc[3][2] += a4.w * b4.z; acc[3][3] += a4.w * b4.w;
        }
        float* outp = gApart + (size_t)s * (FF * FF) + (size_t)(ty * 4) * FF + tx * 4;
#pragma unroll
        for (int i = 0; i < 4; i++) {
            float4 o4 = make_float4(acc[i][0], acc[i][1], acc[i][2], acc[i][3]);
            *reinterpret_cast<float4*>(outp + (size_t)i * FF) = o4;
        }
    } else {
        // u[f] = sum_d cp[d]*M[d][f] / D ; mbar[f] = sum_d M[d][f] / D
        __shared__ float sCp[DD];
        __shared__ float sRu[4 * 64];
        __shared__ float sRm[4 * 64];
        if (tid < 256) {
            sCp[tid] = gCp[tid];
            sCp[256 + tid] = gCp[256 + tid];
        }
        __syncthreads();
        const int f = tid & 63, q = tid >> 6;
        float accU = 0.f, accM = 0.f;
        for (int dl = 0; dl < 128; dl++) {
            int d = q * 128 + dl;
            float m = 0.f;
#pragma unroll
            for (int sl = 0; sl < NSL; sl++) m += gMpart[(size_t)sl * (DD * FF) + (size_t)d * FF + f];
            accU += sCp[d] * m;
            accM += m;
        }
        sRu[q * 64 + f] = accU;
        sRm[q * 64 + f] = accM;
        __syncthreads();
        if (tid < 64) {
            float tu = sRu[tid] + sRu[64 + tid] + sRu[128 + tid] + sRu[192 + tid];
            float tm = sRm[tid] + sRm[64 + tid] + sRm[128 + tid] + sRm[192 + tid];
            gU[tid] = tu * (1.0f / DD);
            gMbar[tid] = tm * (1.0f / DD);
        }
    }
}

// ---------------------------------------------------------------------------
// K3: per-batch truncated EMA, warp-per-timestep variance, coalesced GEMV.
//     grid(B), block(256).
// ---------------------------------------------------------------------------
__global__ void k3(const float* __restrict__ x,
                   const float* __restrict__ th1, const float* __restrict__ ph1,
                   const float* __restrict__ th2, const float* __restrict__ ph2,
                   const float* __restrict__ w1p, const float* __restrict__ w2p,
                   const float* __restrict__ bgp,
                   const float* __restrict__ gamma, const float* __restrict__ beta,
                   float* __restrict__ out) {
    __shared__ float sA[64 * 65];
    __shared__ float sU[64], sMb[64], sxt[64];
    __shared__ float sxc[8][64];
    __shared__ float scoef[8];
    const int tid = threadIdx.x;
    const int b = blockIdx.x;
    const int wj = tid >> 5, lane = tid & 31;

    // prologue: reduce A partials + center
#pragma unroll
    for (int i = 0; i < 16; i++) {
        int e = i * 256 + tid;              // 0..4095
        int f1 = e >> 6, f2 = e & 63;
        float acc = 0.f;
#pragma unroll
        for (int sl = 0; sl < NSL; sl++) acc += gApart[(size_t)sl * (FF * FF) + e];
        sA[f1 * 65 + f2] = acc * (1.0f / DD) - gMbar[f1] * gMbar[f2];
    }
    if (tid < 64) { sU[tid] = gU[tid]; sMb[tid] = gMbar[tid]; }
    const float v = gV[0];

    // gate
    const float z1 = cosf(th1[0]) * cosf(ph1[0]);
    const float z2 = cosf(th2[0]) * cosf(ph2[0]);
    const float zg = w1p[0] * z1 + w2p[0] * z2 + bgp[0];
    float g = 1.0f / (1.0f + expf(-zg));
    g = fminf(fmaxf(g, G_MIN), G_MAX);
    const float omg = 1.0f - g;
    const float l2omg = log2f(omg);
    int n = (int)ceilf(-23.03f / logf(omg));
    if (n < 1) n = 1;
    if (n > TT) n = TT;
    __syncthreads();

    const float* xb = x + (size_t)b * TT * FF;
    float xacc = 0.f;   // threads 0..63: Xtilde[tid]
    float Sacc = 0.f;   // all threads (redundant)

    for (int j0 = 0; j0 < n; j0 += 8) {
        const int j = j0 + wj;
        const bool valid = (j < n);
        const int t = TT - 1 - j;
        float xa = 0.f, xb2 = 0.f;
        if (valid) {
            xa  = xb[(size_t)t * FF + lane];
            xb2 = xb[(size_t)t * FF + 32 + lane];
        }
        sxc[wj][lane] = xa;
        sxc[wj][32 + lane] = xb2;
        __syncwarp();
        float aca = 0.f, acb = 0.f;
#pragma unroll 8
        for (int f2 = 0; f2 < 64; f2++) {
            float xv = sxc[wj][f2];
            aca += sA[lane * 65 + f2] * xv;
            acb += sA[(32 + lane) * 65 + f2] * xv;
        }
        float p = xa * (aca + 2.0f * sU[lane]) + xb2 * (acb + 2.0f * sU[32 + lane]);
#pragma unroll
        for (int o = 16; o > 0; o >>= 1) p += __shfl_down_sync(0xffffffffu, p, o);
        if (lane == 0) {
            float var = p + v;
            float s = rsqrtf(var + LN_EPS);
            float w = g * exp2f((float)j * l2omg);
            scoef[wj] = valid ? (w * s) : 0.f;
        }
        __syncthreads();
        // combine chunk
        if (tid < 64) {
#pragma unroll
            for (int jj = 0; jj < 8; jj++) xacc += scoef[jj] * sxc[jj][tid];
        }
#pragma unroll
        for (int jj = 0; jj < 8; jj++) Sacc += scoef[jj];
        __syncthreads();
    }

    if (tid < 64) sxt[tid] = xacc;
    __syncthreads();

    const float Wsum = 1.0f - exp2f((float)TT * l2omg);
    // mdot = sum_f mbar[f]*Xtilde[f]  (redundant per-thread, broadcast LDS)
    float mdot = 0.f;
#pragma unroll 8
    for (int f = 0; f < 64; f++) mdot += sMb[f] * sxt[f];

    // GEMV: h[d] = gamma[d]*(sum_f M[d][f]*Xt[f] - mdot + cp[d]*S) + beta[d]*Wsum
    float* ob = out + (size_t)b * DD;
    float dot0 = 0.f, dot1 = 0.f;
#pragma unroll 8
    for (int f = 0; f < 64; f++) {
        float xf = sxt[f];
        dot0 += gMt[(size_t)f * DD + tid] * xf;
        dot1 += gMt[(size_t)f * DD + 256 + tid] * xf;
    }
    ob[tid]       = gamma[tid]       * (dot0 - mdot + gCp[tid]       * Sacc) + beta[tid]       * Wsum;
    ob[256 + tid] = gamma[256 + tid] * (dot1 - mdot + gCp[256 + tid] * Sacc) + beta[256 + tid] * Wsum;
}

// ---------------------------------------------------------------------------
// Inputs: x, theta1, phi1, theta2, phi2, w1, w2, b_g, P_w, W_w, W_b, b,
//         ln_gamma, ln_beta, alpha (alpha cancels inside LayerNorm).
// ---------------------------------------------------------------------------
extern "C" void kernel_launch(void* const* d_in, const int* in_sizes, int n_in,
                              void* d_out, int out_size) {
    const float* x     = (const float*)d_in[0];
    const float* th1   = (const float*)d_in[1];
    const float* ph1   = (const float*)d_in[2];
    const float* th2   = (const float*)d_in[3];
    const float* ph2   = (const float*)d_in[4];
    const float* w1p   = (const float*)d_in[5];
    const float* w2p   = (const float*)d_in[6];
    const float* bgp   = (const float*)d_in[7];
    const float* Pw    = (const float*)d_in[8];
    const float* Ww    = (const float*)d_in[9];
    const float* Wb    = (const float*)d_in[10];
    const float* bvec  = (const float*)d_in[11];
    const float* gamma = (const float*)d_in[12];
    const float* beta  = (const float*)d_in[13];

    k1<<<65, 256>>>(Ww, Pw, Wb, bvec);
    k2<<<9, 256>>>(0);
    k3<<<BB, 256>>>(x, th1, ph1, th2, ph2, w1p, w2p, bgp, gamma, beta, (float*)d_out);
}

// round 3
// speedup vs baseline: 1.7071x; 1.1221x over previous
#include <cuda_runtime.h>
#include <math.h>

#define BB 64
#define TT 2048
#define FF 64
#define KK 512
#define DD 512
#define LN_EPS 1e-5f
#define G_MIN 0.05f
#define G_MAX 0.95f
#define NSL 16         // split-K slices in k1
#define NDS 8          // d-slices in k2

// Scratch (__device__ globals; no allocation allowed)
__device__ __align__(16) float gMpart[NSL * DD * FF];   // split-K partials of M   2MB
__device__ __align__(16) float gApart[NDS * FF * FF];   // split-D partials of raw A
__device__ __align__(16) float gUpart[NDS * FF];        // split-D partials of u (raw)
__device__ __align__(16) float gMbarpart[NDS * FF];     // split-D partials of col sums
__device__ __align__(16) float gMt[FF * DD];            // M transposed [f][d]
__device__ __align__(16) float gCp[DD];                 // c' = (W_b+b) - mean
__device__ float gV[1];                                 // |c'|^2 / D

// ---------------------------------------------------------------------------
// K1: blocks 0..127: split-K tiled GEMM (16 k-slices x 8 d-tiles),
//     tile 64d x 64f x 32k, 256 threads, 4x4 micro-tiles.
//     block 128: c' / cbar / v.
// ---------------------------------------------------------------------------
__global__ void k1(const float* __restrict__ Ww, const float* __restrict__ Pw,
                   const float* __restrict__ Wb, const float* __restrict__ bvec) {
    const int tid = threadIdx.x;

    if (blockIdx.x < 128) {
        __shared__ float sAt[32 * 65];   // Ww tile transposed: [k][d]
        __shared__ float sB[32 * 64];    // Pw tile: [k][f]
        const int ct = blockIdx.x & 7;        // d tile
        const int ks = blockIdx.x >> 3;       // k slice
        const int d0 = ct * 64, k0 = ks * 32;

#pragma unroll
        for (int i = 0; i < 2; i++) {
            int idx4 = i * 256 + tid;          // 0..511
            // Ww tile: 64 rows x 32 k = 512 float4
            int kq = idx4 & 7, dy = idx4 >> 3;
            float4 w4 = *reinterpret_cast<const float4*>(Ww + (size_t)(d0 + dy) * KK + k0 + kq * 4);
            sAt[(kq * 4 + 0) * 65 + dy] = w4.x;
            sAt[(kq * 4 + 1) * 65 + dy] = w4.y;
            sAt[(kq * 4 + 2) * 65 + dy] = w4.z;
            sAt[(kq * 4 + 3) * 65 + dy] = w4.w;
            // Pw tile: 32 rows x 64 f = 512 float4
            int fq = idx4 & 15, ky = idx4 >> 4;
            float4 p4 = *reinterpret_cast<const float4*>(Pw + (size_t)(k0 + ky) * FF + fq * 4);
            *reinterpret_cast<float4*>(sB + ky * 64 + fq * 4) = p4;
        }
        __syncthreads();

        const int tx = tid & 15, ty = tid >> 4;
        float acc[4][4];
#pragma unroll
        for (int i = 0; i < 4; i++)
#pragma unroll
            for (int j = 0; j < 4; j++) acc[i][j] = 0.f;

#pragma unroll 4
        for (int k = 0; k < 32; k++) {
            float a0 = sAt[k * 65 + ty * 4 + 0];
            float a1 = sAt[k * 65 + ty * 4 + 1];
            float a2 = sAt[k * 65 + ty * 4 + 2];
            float a3 = sAt[k * 65 + ty * 4 + 3];
            float4 b4 = *reinterpret_cast<const float4*>(sB + k * 64 + tx * 4);
            acc[0][0] += a0 * b4.x; acc[0][1] += a0 * b4.y; acc[0][2] += a0 * b4.z; acc[0][3] += a0 * b4.w;
            acc[1][0] += a1 * b4.x; acc[1][1] += a1 * b4.y; acc[1][2] += a1 * b4.z; acc[1][3] += a1 * b4.w;
            acc[2][0] += a2 * b4.x; acc[2][1] += a2 * b4.y; acc[2][2] += a2 * b4.z; acc[2][3] += a2 * b4.w;
            acc[3][0] += a3 * b4.x; acc[3][1] += a3 * b4.y; acc[3][2] += a3 * b4.z; acc[3][3] += a3 * b4.w;
        }
        float* outp = gMpart + (size_t)ks * (DD * FF) + (size_t)(d0 + ty * 4) * FF + tx * 4;
#pragma unroll
        for (int i = 0; i < 4; i++) {
            float4 o4 = make_float4(acc[i][0], acc[i][1], acc[i][2], acc[i][3]);
            *reinterpret_cast<float4*>(outp + (size_t)i * FF) = o4;
        }
    } else {
        // c = W_b + b ; c' = c - mean(c) ; v = |c'|^2/D
        __shared__ float sred[64];
        float cv[8];
        float ssum = 0.f;
        if (tid < 64) {
#pragma unroll
            for (int i = 0; i < 8; i++) {
                cv[i] = Wb[i * 64 + tid] + bvec[i * 64 + tid];
                ssum += cv[i];
            }
            sred[tid] = ssum;
        }
        __syncthreads();
        for (int o = 32; o > 0; o >>= 1) {
            if (tid < o) sred[tid] += sred[tid + o];
            __syncthreads();
        }
        const float cbar = sred[0] * (1.0f / DD);
        __syncthreads();
        float vsum = 0.f;
        if (tid < 64) {
#pragma unroll
            for (int i = 0; i < 8; i++) {
                float cp = cv[i] - cbar;
                gCp[i * 64 + tid] = cp;
                vsum += cp * cp;
            }
            sred[tid] = vsum;
        }
        __syncthreads();
        for (int o = 32; o > 0; o >>= 1) {
            if (tid < o) sred[tid] += sred[tid + o];
            __syncthreads();
        }
        if (tid == 0) gV[0] = sred[0] * (1.0f / DD);
    }
}

// ---------------------------------------------------------------------------
// K2: grid(8), block(256). Block s (d-slice of 64 rows):
//   - reduce 16 split-K partials -> sS (shared)
//   - write gMt slice (transposed)
//   - Apart[s] = sS^T sS
//   - uPart[s][f] = sum_{d in slice} cp[d]*sS[d][f];  mbarPart likewise
// ---------------------------------------------------------------------------
__global__ void k2(int dummy) {
    __shared__ float sS[64 * 68];     // reduced M slice [d][f], padded
    __shared__ float sCpS[64];
    __shared__ float sRu[4 * 64];
    __shared__ float sRm[4 * 64];
    const int tid = threadIdx.x;
    const int s = blockIdx.x;

    if (tid < 64) sCpS[tid] = gCp[s * 64 + tid];

    // reduce 16 partials for this slice
#pragma unroll
    for (int i = 0; i < 16; i++) {
        int e = i * 256 + tid;          // 0..4095
        int dl = e >> 6, f = e & 63;
        size_t off = (size_t)(s * 64 + dl) * FF + f;
        float acc = 0.f;
#pragma unroll
        for (int sl = 0; sl < NSL; sl++) acc += gMpart[(size_t)sl * (DD * FF) + off];
        sS[dl * 68 + f] = acc;
    }
    __syncthreads();

    // write M transposed: gMt[f*512 + s*64 + dl]
#pragma unroll
    for (int i = 0; i < 16; i++) {
        int e = i * 256 + tid;
        int f = e >> 6, dl = e & 63;
        gMt[(size_t)f * DD + s * 64 + dl] = sS[dl * 68 + f];
    }

    // uPart / mbarPart from shared
    {
        const int f = tid & 63, q = tid >> 6;
        float accU = 0.f, accM = 0.f;
#pragma unroll
        for (int i = 0; i < 16; i++) {
            int dl = q * 16 + i;
            float m = sS[dl * 68 + f];
            accU += sCpS[dl] * m;
            accM += m;
        }
        sRu[q * 64 + f] = accU;
        sRm[q * 64 + f] = accM;
    }
    __syncthreads();
    if (tid < 64) {
        gUpart[s * 64 + tid]    = sRu[tid] + sRu[64 + tid] + sRu[128 + tid] + sRu[192 + tid];
        gMbarpart[s * 64 + tid] = sRm[tid] + sRm[64 + tid] + sRm[128 + tid] + sRm[192 + tid];
    }

    // Apart[s][f1][f2] = sum_d sS[d][f1]*sS[d][f2]
    const int tx = tid & 15, ty = tid >> 4;
    float acc[4][4];
#pragma unroll
    for (int i = 0; i < 4; i++)
#pragma unroll
        for (int j = 0; j < 4; j++) acc[i][j] = 0.f;
#pragma unroll 4
    for (int d = 0; d < 64; d++) {
        float4 a4 = *reinterpret_cast<const float4*>(sS + d * 68 + ty * 4);
        float4 b4 = *reinterpret_cast<const float4*>(sS + d * 68 + tx * 4);
        acc[0][0] += a4.x * b4.x; acc[0][1] += a4.x * b4.y; acc[0][2] += a4.x * b4.z; acc[0][3] += a4.x * b4.w;
        acc[1][0] += a4.y * b4.x; acc[1][1] += a4.y * b4.y; acc[1][2] += a4.y * b4.z; acc[1][3] += a4.y * b4.w;
        acc[2][0] += a4.z * b4.x; acc[2][1] += a4.z * b4.y; acc[2][2] += a4.z * b4.z; acc[2][3] += a4.z * b4.w;
        acc[3][0] += a4.w * b4.x; acc[3][1] += a4.w * b4.y; acc[3][2] += a4.w * b4.z; acc[3][3] += a4.w * b4.w;
    }
    float* outp = gApart + (size_t)s * (FF * FF) + (size_t)(ty * 4) * FF + tx * 4;
#pragma unroll
    for (int i = 0; i < 4; i++) {
        float4 o4 = make_float4(acc[i][0], acc[i][1], acc[i][2], acc[i][3]);
        *reinterpret_cast<float4*>(outp + (size_t)i * FF) = o4;
    }
}

// ---------------------------------------------------------------------------
// K3: per-batch truncated EMA, warp-per-timestep variance, coalesced GEMV.
//     grid(B), block(256). Prologue reduces A/u/mbar partials.
// ---------------------------------------------------------------------------
__global__ void k3(const float* __restrict__ x,
                   const float* __restrict__ th1, const float* __restrict__ ph1,
                   const float* __restrict__ th2, const float* __restrict__ ph2,
                   const float* __restrict__ w1p, const float* __restrict__ w2p,
                   const float* __restrict__ bgp,
                   const float* __restrict__ gamma, const float* __restrict__ beta,
                   float* __restrict__ out) {
    __shared__ float sA[64 * 65];
    __shared__ float sU[64], sMb[64], sxt[64];
    __shared__ float sxc[8][64];
    __shared__ float scoef[8];
    const int tid = threadIdx.x;
    const int b = blockIdx.x;
    const int wj = tid >> 5, lane = tid & 31;

    // reduce u / mbar partials first (needed for centering A)
    if (tid < 64) {
        float tu = 0.f, tm = 0.f;
#pragma unroll
        for (int s = 0; s < NDS; s++) {
            tu += gUpart[s * 64 + tid];
            tm += gMbarpart[s * 64 + tid];
        }
        sU[tid] = tu * (1.0f / DD);
        sMb[tid] = tm * (1.0f / DD);
    }
    __syncthreads();

    // reduce + center A
#pragma unroll
    for (int i = 0; i < 16; i++) {
        int e = i * 256 + tid;              // 0..4095
        int f1 = e >> 6, f2 = e & 63;
        float acc = 0.f;
#pragma unroll
        for (int sl = 0; sl < NDS; sl++) acc += gApart[(size_t)sl * (FF * FF) + e];
        sA[f1 * 65 + f2] = acc * (1.0f / DD) - sMb[f1] * sMb[f2];
    }
    const float v = gV[0];

    // gate
    const float z1 = cosf(th1[0]) * cosf(ph1[0]);
    const float z2 = cosf(th2[0]) * cosf(ph2[0]);
    const float zg = w1p[0] * z1 + w2p[0] * z2 + bgp[0];
    float g = 1.0f / (1.0f + expf(-zg));
    g = fminf(fmaxf(g, G_MIN), G_MAX);
    const float omg = 1.0f - g;
    const float l2omg = log2f(omg);
    int n = (int)ceilf(-23.03f / logf(omg));
    if (n < 1) n = 1;
    if (n > TT) n = TT;
    __syncthreads();

    const float* xb = x + (size_t)b * TT * FF;
    float xacc = 0.f;   // threads 0..63: Xtilde[tid]
    float Sacc = 0.f;   // all threads (redundant)

    for (int j0 = 0; j0 < n; j0 += 8) {
        const int j = j0 + wj;
        const bool valid = (j < n);
        const int t = TT - 1 - j;
        float xa = 0.f, xb2 = 0.f;
        if (valid) {
            xa  = xb[(size_t)t * FF + lane];
            xb2 = xb[(size_t)t * FF + 32 + lane];
        }
        sxc[wj][lane] = xa;
        sxc[wj][32 + lane] = xb2;
        __syncwarp();
        float aca = 0.f, acb = 0.f;
#pragma unroll 8
        for (int f2 = 0; f2 < 64; f2++) {
            float xv = sxc[wj][f2];
            aca += sA[lane * 65 + f2] * xv;
            acb += sA[(32 + lane) * 65 + f2] * xv;
        }
        float p = xa * (aca + 2.0f * sU[lane]) + xb2 * (acb + 2.0f * sU[32 + lane]);
#pragma unroll
        for (int o = 16; o > 0; o >>= 1) p += __shfl_down_sync(0xffffffffu, p, o);
        if (lane == 0) {
            float var = p + v;
            float s = rsqrtf(var + LN_EPS);
            float w = g * exp2f((float)j * l2omg);
            scoef[wj] = valid ? (w * s) : 0.f;
        }
        __syncthreads();
        if (tid < 64) {
#pragma unroll
            for (int jj = 0; jj < 8; jj++) xacc += scoef[jj] * sxc[jj][tid];
        }
#pragma unroll
        for (int jj = 0; jj < 8; jj++) Sacc += scoef[jj];
        __syncthreads();
    }

    if (tid < 64) sxt[tid] = xacc;
    __syncthreads();

    const float Wsum = 1.0f - exp2f((float)TT * l2omg);
    float mdot = 0.f;
#pragma unroll 8
    for (int f = 0; f < 64; f++) mdot += sMb[f] * sxt[f];

    // GEMV: h[d] = gamma[d]*(sum_f M[d][f]*Xt[f] - mdot + cp[d]*S) + beta[d]*Wsum
    float* ob = out + (size_t)b * DD;
    float dot0 = 0.f, dot1 = 0.f;
#pragma unroll 8
    for (int f = 0; f < 64; f++) {
        float xf = sxt[f];
        dot0 += gMt[(size_t)f * DD + tid] * xf;
        dot1 += gMt[(size_t)f * DD + 256 + tid] * xf;
    }
    ob[tid]       = gamma[tid]       * (dot0 - mdot + gCp[tid]       * Sacc) + beta[tid]       * Wsum;
    ob[256 + tid] = gamma[256 + tid] * (dot1 - mdot + gCp[256 + tid] * Sacc) + beta[256 + tid] * Wsum;
}

// ---------------------------------------------------------------------------
// Inputs: x, theta1, phi1, theta2, phi2, w1, w2, b_g, P_w, W_w, W_b, b,
//         ln_gamma, ln_beta, alpha (alpha cancels inside LayerNorm).
// ---------------------------------------------------------------------------
extern "C" void kernel_launch(void* const* d_in, const int* in_sizes, int n_in,
                              void* d_out, int out_size) {
    const float* x     = (const float*)d_in[0];
    const float* th1   = (const float*)d_in[1];
    const float* ph1   = (const float*)d_in[2];
    const float* th2   = (const float*)d_in[3];
    const float* ph2   = (const float*)d_in[4];
    const float* w1p   = (const float*)d_in[5];
    const float* w2p   = (const float*)d_in[6];
    const float* bgp   = (const float*)d_in[7];
    const float* Pw    = (const float*)d_in[8];
    const float* Ww    = (const float*)d_in[9];
    const float* Wb    = (const float*)d_in[10];
    const float* bvec  = (const float*)d_in[11];
    const float* gamma = (const float*)d_in[12];
    const float* beta  = (const float*)d_in[13];

    k1<<<129, 256>>>(Ww, Pw, Wb, bvec);
    k2<<<NDS, 256>>>(0);
    k3<<<BB, 256>>>(x, th1, ph1, th2, ph2, w1p, w2p, bgp, gamma, beta, (float*)d_out);
}

// round 7
// speedup vs baseline: 2.3174x; 1.3575x over previous
#include <cuda_runtime.h>
#include <math.h>

#define BB 64
#define TT 2048
#define FF 64
#define KK 512
#define DD 512
#define LN_EPS 1e-5f
#define G_MIN 0.05f
#define G_MAX 0.95f
#define NSL 8          // k-slices (phase 1)
#define NDS 8          // d-slices (phase 2)
#define GRID 65

// Scratch (__device__ globals; no allocation allowed)
__device__ __align__(16) float gMpart[NSL * DD * FF];   // split-K partials of M
__device__ __align__(16) float gApart[NDS * FF * FF];   // split-D partials of raw A
__device__ __align__(16) float gUpart[NDS * FF];
__device__ __align__(16) float gMbarpart[NDS * FF];
__device__ __align__(16) float gMt[FF * DD];            // M transposed [f][d]
__device__ __align__(16) float gCp[DD];                 // c' = (W_b+b) - mean
__device__ float gV[1];                                 // |c'|^2 / D
__device__ unsigned int gBarCnt[2];                     // monotonic ticket barriers

// Grid-wide barrier: all GRID blocks resident (GRID=65 <= 148 SMs, 1 blk/SM),
// monotonic counter so no reset is needed across graph replays.
__device__ __forceinline__ void grid_bar(int which) {
    __syncthreads();
    if (threadIdx.x == 0) {
        __threadfence();                                 // release prior writes
        unsigned int t = atomicAdd(&gBarCnt[which], 1u);
        unsigned int target = (t / GRID + 1u) * GRID;
        volatile unsigned int* p = &gBarCnt[which];
        while (*p < target) { }
        __threadfence();                                 // acquire
    }
    __syncthreads();
}

__global__ void __launch_bounds__(256, 1)
mega(const float* __restrict__ x,
     const float* __restrict__ th1, const float* __restrict__ ph1,
     const float* __restrict__ th2, const float* __restrict__ ph2,
     const float* __restrict__ w1p, const float* __restrict__ w2p,
     const float* __restrict__ bgp,
     const float* __restrict__ Pw,  const float* __restrict__ Ww,
     const float* __restrict__ Wb,  const float* __restrict__ bvec,
     const float* __restrict__ gamma, const float* __restrict__ beta,
     float* __restrict__ out) {
    __shared__ float sPool[8256];          // 33KB, aliased per phase
    __shared__ float sCpS[64];
    __shared__ float sR1[256];
    __shared__ float sR2[256];
    __shared__ float sU[64], sMb[64], sxt[64];
    __shared__ float sxc[8][64];
    __shared__ float scoef[8];

    const int tid = threadIdx.x;
    const int bid = blockIdx.x;

    // ---- gate scalars (needed by blocks 0..63 for prefetch + phase 3) ----
    float g = 0.f, omg = 0.f, l2omg = 0.f;
    int n = 0;
    if (bid < 64) {
        const float z1 = cosf(th1[0]) * cosf(ph1[0]);
        const float z2 = cosf(th2[0]) * cosf(ph2[0]);
        const float zg = w1p[0] * z1 + w2p[0] * z2 + bgp[0];
        g = 1.0f / (1.0f + expf(-zg));
        g = fminf(fmaxf(g, G_MIN), G_MAX);
        omg = 1.0f - g;
        l2omg = log2f(omg);
        n = (int)ceilf(-23.03f / logf(omg));
        if (n < 1) n = 1;
        if (n > TT) n = TT;

        // L2 prefetch of this batch's x tail (warms phase 3)
        const float* xb = x + (size_t)bid * TT * FF;
        int np = n > 96 ? 96 : n;
        for (int r = tid; r < np * 2; r += 256) {
            int j = r >> 1;
            const float* a = xb + (size_t)(TT - 1 - j) * FF + (r & 1) * 32;
            asm volatile("prefetch.global.L2 [%0];" :: "l"(a));
        }
    }

    // ================= Phase 1 =================
    if (bid < 64) {
        float* sAt = sPool;                 // [k][d] 64x65
        float* sB  = sPool + 64 * 65;       // [k][f] 64x64
        const int ct = bid & 7;             // d tile
        const int ks = bid >> 3;            // k slice
        const int d0 = ct * 64, k0 = ks * 64;

#pragma unroll
        for (int i = 0; i < 4; i++) {
            int idx4 = i * 256 + tid;       // 0..1023
            int kq = idx4 & 15, dy = idx4 >> 4;
            float4 w4 = *reinterpret_cast<const float4*>(Ww + (size_t)(d0 + dy) * KK + k0 + kq * 4);
            sAt[(kq * 4 + 0) * 65 + dy] = w4.x;
            sAt[(kq * 4 + 1) * 65 + dy] = w4.y;
            sAt[(kq * 4 + 2) * 65 + dy] = w4.z;
            sAt[(kq * 4 + 3) * 65 + dy] = w4.w;
            int fq = idx4 & 15, ky = idx4 >> 4;
            float4 p4 = *reinterpret_cast<const float4*>(Pw + (size_t)(k0 + ky) * FF + fq * 4);
            *reinterpret_cast<float4*>(sB + ky * 64 + fq * 4) = p4;
        }
        __syncthreads();

        const int tx = tid & 15, ty = tid >> 4;
        float acc[4][4];
#pragma unroll
        for (int i = 0; i < 4; i++)
#pragma unroll
            for (int j = 0; j < 4; j++) acc[i][j] = 0.f;

#pragma unroll 4
        for (int k = 0; k < 64; k++) {
            float a0 = sAt[k * 65 + ty * 4 + 0];
            float a1 = sAt[k * 65 + ty * 4 + 1];
            float a2 = sAt[k * 65 + ty * 4 + 2];
            float a3 = sAt[k * 65 + ty * 4 + 3];
            float4 b4 = *reinterpret_cast<const float4*>(sB + k * 64 + tx * 4);
            acc[0][0] += a0 * b4.x; acc[0][1] += a0 * b4.y; acc[0][2] += a0 * b4.z; acc[0][3] += a0 * b4.w;
            acc[1][0] += a1 * b4.x; acc[1][1] += a1 * b4.y; acc[1][2] += a1 * b4.z; acc[1][3] += a1 * b4.w;
            acc[2][0] += a2 * b4.x; acc[2][1] += a2 * b4.y; acc[2][2] += a2 * b4.z; acc[2][3] += a2 * b4.w;
            acc[3][0] += a3 * b4.x; acc[3][1] += a3 * b4.y; acc[3][2] += a3 * b4.z; acc[3][3] += a3 * b4.w;
        }
        float* outp = gMpart + (size_t)ks * (DD * FF) + (size_t)(d0 + ty * 4) * FF + tx * 4;
#pragma unroll
        for (int i = 0; i < 4; i++) {
            float4 o4 = make_float4(acc[i][0], acc[i][1], acc[i][2], acc[i][3]);
            *reinterpret_cast<float4*>(outp + (size_t)i * FF) = o4;
        }
    } else {
        // block 64: c' / cbar / v
        float cv[8];
        float ssum = 0.f;
        if (tid < 64) {
#pragma unroll
            for (int i = 0; i < 8; i++) {
                cv[i] = Wb[i * 64 + tid] + bvec[i * 64 + tid];
                ssum += cv[i];
            }
            sR1[tid] = ssum;
        }
        __syncthreads();
        for (int o = 32; o > 0; o >>= 1) {
            if (tid < o) sR1[tid] += sR1[tid + o];
            __syncthreads();
        }
        const float cbar = sR1[0] * (1.0f / DD);
        __syncthreads();
        float vsum = 0.f;
        if (tid < 64) {
#pragma unroll
            for (int i = 0; i < 8; i++) {
                float cp = cv[i] - cbar;
                gCp[i * 64 + tid] = cp;
                vsum += cp * cp;
            }
            sR1[tid] = vsum;
        }
        __syncthreads();
        for (int o = 32; o > 0; o >>= 1) {
            if (tid < o) sR1[tid] += sR1[tid + o];
            __syncthreads();
        }
        if (tid == 0) gV[0] = sR1[0] * (1.0f / DD);
    }

    grid_bar(0);

    // ================= Phase 2: blocks 0..7 =================
    if (bid < NDS) {
        float* sS = sPool;                  // [d][f] stride 68 (4352 floats)
        const int s = bid;
        if (tid < 64) sCpS[tid] = gCp[s * 64 + tid];

#pragma unroll
        for (int i = 0; i < 16; i++) {
            int e = i * 256 + tid;          // 0..4095
            int dl = e >> 6, f = e & 63;
            size_t off = (size_t)(s * 64 + dl) * FF + f;
            float acc = 0.f;
#pragma unroll
            for (int sl = 0; sl < NSL; sl++) acc += gMpart[(size_t)sl * (DD * FF) + off];
            sS[dl * 68 + f] = acc;
        }
        __syncthreads();

        // write M transposed
#pragma unroll
        for (int i = 0; i < 16; i++) {
            int e = i * 256 + tid;
            int f = e >> 6, dl = e & 63;
            gMt[(size_t)f * DD + s * 64 + dl] = sS[dl * 68 + f];
        }

        // uPart / mbarPart
        {
            const int f = tid & 63, q = tid >> 6;
            float accU = 0.f, accM = 0.f;
#pragma unroll
            for (int i = 0; i < 16; i++) {
                int dl = q * 16 + i;
                float m = sS[dl * 68 + f];
                accU += sCpS[dl] * m;
                accM += m;
            }
            sR1[q * 64 + f] = accU;
            sR2[q * 64 + f] = accM;
        }
        __syncthreads();
        if (tid < 64) {
            gUpart[s * 64 + tid]    = sR1[tid] + sR1[64 + tid] + sR1[128 + tid] + sR1[192 + tid];
            gMbarpart[s * 64 + tid] = sR2[tid] + sR2[64 + tid] + sR2[128 + tid] + sR2[192 + tid];
        }

        // Apart[s] = sS^T sS
        const int tx = tid & 15, ty = tid >> 4;
        float acc[4][4];
#pragma unroll
        for (int i = 0; i < 4; i++)
#pragma unroll
            for (int j = 0; j < 4; j++) acc[i][j] = 0.f;
#pragma unroll 4
        for (int d = 0; d < 64; d++) {
            float4 a4 = *reinterpret_cast<const float4*>(sS + d * 68 + ty * 4);
            float4 b4 = *reinterpret_cast<const float4*>(sS + d * 68 + tx * 4);
            acc[0][0] += a4.x * b4.x; acc[0][1] += a4.x * b4.y; acc[0][2] += a4.x * b4.z; acc[0][3] += a4.x * b4.w;
            acc[1][0] += a4.y * b4.x; acc[1][1] += a4.y * b4.y; acc[1][2] += a4.y * b4.z; acc[1][3] += a4.y * b4.w;
            acc[2][0] += a4.z * b4.x; acc[2][1] += a4.z * b4.y; acc[2][2] += a4.z * b4.z; acc[2][3] += a4.z * b4.w;
            acc[3][0] += a4.w * b4.x; acc[3][1] += a4.w * b4.y; acc[3][2] += a4.w * b4.z; acc[3][3] += a4.w * b4.w;
        }
        float* outp = gApart + (size_t)s * (FF * FF) + (size_t)(ty * 4) * FF + tx * 4;
#pragma unroll
        for (int i = 0; i < 4; i++) {
            float4 o4 = make_float4(acc[i][0], acc[i][1], acc[i][2], acc[i][3]);
            *reinterpret_cast<float4*>(outp + (size_t)i * FF) = o4;
        }
    }

    grid_bar(1);

    // ================= Phase 3: blocks 0..63 =================
    if (bid >= 64) return;
    {
        float* sA = sPool;                  // stride 65 (4160 floats)
        const int b = bid;
        const int wj = tid >> 5, lane = tid & 31;

        if (tid < 64) {
            float tu = 0.f, tm = 0.f;
#pragma unroll
            for (int s = 0; s < NDS; s++) {
                tu += gUpart[s * 64 + tid];
                tm += gMbarpart[s * 64 + tid];
            }
            sU[tid] = tu * (1.0f / DD);
            sMb[tid] = tm * (1.0f / DD);
        }
        __syncthreads();

#pragma unroll
        for (int i = 0; i < 16; i++) {
            int e = i * 256 + tid;
            int f1 = e >> 6, f2 = e & 63;
            float acc = 0.f;
#pragma unroll
            for (int sl = 0; sl < NDS; sl++) acc += gApart[(size_t)sl * (FF * FF) + e];
            sA[f1 * 65 + f2] = acc * (1.0f / DD) - sMb[f1] * sMb[f2];
        }
        const float v = gV[0];
        __syncthreads();

        const float* xb = x + (size_t)b * TT * FF;
        float xacc = 0.f;
        float Sacc = 0.f;

        for (int j0 = 0; j0 < n; j0 += 8) {
            const int j = j0 + wj;
            const bool valid = (j < n);
            const int t = TT - 1 - j;
            float xa = 0.f, xb2 = 0.f;
            if (valid) {
                xa  = xb[(size_t)t * FF + lane];
                xb2 = xb[(size_t)t * FF + 32 + lane];
            }
            sxc[wj][lane] = xa;
            sxc[wj][32 + lane] = xb2;
            __syncwarp();
            float aca = 0.f, acb = 0.f;
#pragma unroll 8
            for (int f2 = 0; f2 < 64; f2++) {
                float xv = sxc[wj][f2];
                aca += sA[lane * 65 + f2] * xv;
                acb += sA[(32 + lane) * 65 + f2] * xv;
            }
            float p = xa * (aca + 2.0f * sU[lane]) + xb2 * (acb + 2.0f * sU[32 + lane]);
#pragma unroll
            for (int o = 16; o > 0; o >>= 1) p += __shfl_down_sync(0xffffffffu, p, o);
            if (lane == 0) {
                float var = p + v;
                float sc = rsqrtf(var + LN_EPS);
                float w = g * exp2f((float)j * l2omg);
                scoef[wj] = valid ? (w * sc) : 0.f;
            }
            __syncthreads();
            if (tid < 64) {
#pragma unroll
                for (int jj = 0; jj < 8; jj++) xacc += scoef[jj] * sxc[jj][tid];
            }
#pragma unroll
            for (int jj = 0; jj < 8; jj++) Sacc += scoef[jj];
            __syncthreads();
        }

        if (tid < 64) sxt[tid] = xacc;
        __syncthreads();

        const float Wsum = 1.0f - exp2f((float)TT * l2omg);
        float mdot = 0.f;
#pragma unroll 8
        for (int f = 0; f < 64; f++) mdot += sMb[f] * sxt[f];

        float* ob = out + (size_t)b * DD;
        float dot0 = 0.f, dot1 = 0.f;
#pragma unroll 8
        for (int f = 0; f < 64; f++) {
            float xf = sxt[f];
            dot0 += gMt[(size_t)f * DD + tid] * xf;
            dot1 += gMt[(size_t)f * DD + 256 + tid] * xf;
        }
        ob[tid]       = gamma[tid]       * (dot0 - mdot + gCp[tid]       * Sacc) + beta[tid]       * Wsum;
        ob[256 + tid] = gamma[256 + tid] * (dot1 - mdot + gCp[256 + tid] * Sacc) + beta[256 + tid] * Wsum;
    }
}

// ---------------------------------------------------------------------------
// Inputs: x, theta1, phi1, theta2, phi2, w1, w2, b_g, P_w, W_w, W_b, b,
//         ln_gamma, ln_beta, alpha (alpha cancels inside LayerNorm).
// ---------------------------------------------------------------------------
extern "C" void kernel_launch(void* const* d_in, const int* in_sizes, int n_in,
                              void* d_out, int out_size) {
    const float* x     = (const float*)d_in[0];
    const float* th1   = (const float*)d_in[1];
    const float* ph1   = (const float*)d_in[2];
    const float* th2   = (const float*)d_in[3];
    const float* ph2   = (const float*)d_in[4];
    const float* w1p   = (const float*)d_in[5];
    const float* w2p   = (const float*)d_in[6];
    const float* bgp   = (const float*)d_in[7];
    const float* Pw    = (const float*)d_in[8];
    const float* Ww    = (const float*)d_in[9];
    const float* Wb    = (const float*)d_in[10];
    const float* bvec  = (const float*)d_in[11];
    const float* gamma = (const float*)d_in[12];
    const float* beta  = (const float*)d_in[13];

    mega<<<GRID, 256>>>(x, th1, ph1, th2, ph2, w1p, w2p, bgp,
                        Pw, Ww, Wb, bvec, gamma, beta, (float*)d_out);
}

// round 8
// speedup vs baseline: 3.0271x; 1.3063x over previous
#include <cuda_runtime.h>
#include <math.h>

#define BB 64
#define TT 2048
#define FF 64
#define KK 512
#define DD 512
#define LN_EPS 1e-5f
#define G_MIN 0.05f
#define G_MAX 0.95f
#define NSL 16         // k-slices (phase 1)
#define NDS 16         // d-slices (phase 2), 32 rows each
#define GRID 129

// Scratch (__device__ globals; no allocation allowed)
__device__ __align__(16) float gMpart[NSL * DD * FF];   // split-K partials of M (2MB)
__device__ __align__(16) float gApart[NDS * FF * FF];   // split-D partials of raw A
__device__ __align__(16) float gUpart[NDS * FF];
__device__ __align__(16) float gMbarpart[NDS * FF];
__device__ __align__(16) float gMt[FF * DD];            // M transposed [f][d]
__device__ __align__(16) float gCp[DD];                 // c' = (W_b+b) - mean
__device__ float gV[1];                                 // |c'|^2 / D
__device__ unsigned int gBarCnt[2];                     // monotonic ticket barriers

// Grid-wide barrier: all GRID blocks resident (regs cap 1 CTA/SM, GRID<=148).
__device__ __forceinline__ void grid_bar(int which) {
    __syncthreads();
    if (threadIdx.x == 0) {
        __threadfence();
        unsigned int t = atomicAdd(&gBarCnt[which], 1u);
        unsigned int target = (t / GRID + 1u) * GRID;
        volatile unsigned int* p = &gBarCnt[which];
        while (*p < target) { }
        __threadfence();
    }
    __syncthreads();
}

__global__ void __launch_bounds__(256, 1)
mega(const float* __restrict__ x,
     const float* __restrict__ th1, const float* __restrict__ ph1,
     const float* __restrict__ th2, const float* __restrict__ ph2,
     const float* __restrict__ w1p, const float* __restrict__ w2p,
     const float* __restrict__ bgp,
     const float* __restrict__ Pw,  const float* __restrict__ Ww,
     const float* __restrict__ Wb,  const float* __restrict__ bvec,
     const float* __restrict__ gamma, const float* __restrict__ beta,
     float* __restrict__ out) {
    __shared__ __align__(16) float sPool[4224];    // phase1: sAt 32x68 + sB 32x64; p2: sS 32x68; p3: sA 64x65
    __shared__ float sCpS[32];
    __shared__ float sR1[256];
    __shared__ float sR2[256];
    __shared__ float sU[64], sMb[64], sxt[64];
    __shared__ float sxc[8][64];
    __shared__ float scoef[8];

    const int tid = threadIdx.x;
    const int bid = blockIdx.x;

    // ---- gate scalars + x-tail L2 prefetch (phase-3 blocks only) ----
    float g = 0.f, omg = 0.f, l2omg = 0.f;
    int n = 0;
    if (bid < 64) {
        const float z1 = cosf(th1[0]) * cosf(ph1[0]);
        const float z2 = cosf(th2[0]) * cosf(ph2[0]);
        const float zg = w1p[0] * z1 + w2p[0] * z2 + bgp[0];
        g = 1.0f / (1.0f + expf(-zg));
        g = fminf(fmaxf(g, G_MIN), G_MAX);
        omg = 1.0f - g;
        l2omg = log2f(omg);
        n = (int)ceilf(-23.03f / logf(omg));
        if (n < 1) n = 1;
        if (n > TT) n = TT;

        const float* xb = x + (size_t)bid * TT * FF;
        int np = n > 96 ? 96 : n;
        for (int r = tid; r < np * 2; r += 256) {
            int j = r >> 1;
            const float* a = xb + (size_t)(TT - 1 - j) * FF + (r & 1) * 32;
            asm volatile("prefetch.global.L2 [%0];" :: "l"(a));
        }
    }

    // ================= Phase 1: 128 GEMM blocks + 1 c'/v block =================
    if (bid < 128) {
        float* sAt = sPool;                 // [k][d] 32x68 (16B-aligned rows)
        float* sB  = sPool + 32 * 68;       // [k][f] 32x64
        const int ct = bid & 7;             // d tile
        const int ks = bid >> 3;            // k slice (16)
        const int d0 = ct * 64, k0 = ks * 32;

#pragma unroll
        for (int i = 0; i < 2; i++) {
            int idx4 = i * 256 + tid;       // 0..511
            int kq = idx4 & 7, dy = idx4 >> 3;     // Ww: 64 d-rows x 8 float4
            float4 w4 = *reinterpret_cast<const float4*>(Ww + (size_t)(d0 + dy) * KK + k0 + kq * 4);
            sAt[(kq * 4 + 0) * 68 + dy] = w4.x;
            sAt[(kq * 4 + 1) * 68 + dy] = w4.y;
            sAt[(kq * 4 + 2) * 68 + dy] = w4.z;
            sAt[(kq * 4 + 3) * 68 + dy] = w4.w;
            int fq = idx4 & 15, ky = idx4 >> 4;    // Pw: 32 k-rows x 16 float4
            float4 p4 = *reinterpret_cast<const float4*>(Pw + (size_t)(k0 + ky) * FF + fq * 4);
            *reinterpret_cast<float4*>(sB + ky * 64 + fq * 4) = p4;
        }
        __syncthreads();

        const int tx = tid & 15, ty = tid >> 4;
        float acc[4][4];
#pragma unroll
        for (int i = 0; i < 4; i++)
#pragma unroll
            for (int j = 0; j < 4; j++) acc[i][j] = 0.f;

#pragma unroll 8
        for (int k = 0; k < 32; k++) {
            float4 a4 = *reinterpret_cast<const float4*>(sAt + k * 68 + ty * 4);
            float4 b4 = *reinterpret_cast<const float4*>(sB + k * 64 + tx * 4);
            acc[0][0] += a4.x * b4.x; acc[0][1] += a4.x * b4.y; acc[0][2] += a4.x * b4.z; acc[0][3] += a4.x * b4.w;
            acc[1][0] += a4.y * b4.x; acc[1][1] += a4.y * b4.y; acc[1][2] += a4.y * b4.z; acc[1][3] += a4.y * b4.w;
            acc[2][0] += a4.z * b4.x; acc[2][1] += a4.z * b4.y; acc[2][2] += a4.z * b4.z; acc[2][3] += a4.z * b4.w;
            acc[3][0] += a4.w * b4.x; acc[3][1] += a4.w * b4.y; acc[3][2] += a4.w * b4.z; acc[3][3] += a4.w * b4.w;
        }
        float* outp = gMpart + (size_t)ks * (DD * FF) + (size_t)(d0 + ty * 4) * FF + tx * 4;
#pragma unroll
        for (int i = 0; i < 4; i++) {
            float4 o4 = make_float4(acc[i][0], acc[i][1], acc[i][2], acc[i][3]);
            *reinterpret_cast<float4*>(outp + (size_t)i * FF) = o4;
        }
    } else {
        // block 128: c' / cbar / v
        float cv[8];
        float ssum = 0.f;
        if (tid < 64) {
#pragma unroll
            for (int i = 0; i < 8; i++) {
                cv[i] = Wb[i * 64 + tid] + bvec[i * 64 + tid];
                ssum += cv[i];
            }
            sR1[tid] = ssum;
        }
        __syncthreads();
        for (int o = 32; o > 0; o >>= 1) {
            if (tid < o) sR1[tid] += sR1[tid + o];
            __syncthreads();
        }
        const float cbar = sR1[0] * (1.0f / DD);
        __syncthreads();
        float vsum = 0.f;
        if (tid < 64) {
#pragma unroll
            for (int i = 0; i < 8; i++) {
                float cp = cv[i] - cbar;
                gCp[i * 64 + tid] = cp;
                vsum += cp * cp;
            }
            sR1[tid] = vsum;
        }
        __syncthreads();
        for (int o = 32; o > 0; o >>= 1) {
            if (tid < o) sR1[tid] += sR1[tid + o];
            __syncthreads();
        }
        if (tid == 0) gV[0] = sR1[0] * (1.0f / DD);
    }

    grid_bar(0);

    // ================= Phase 2: blocks 0..15, d-slices of 32 rows =================
    if (bid < NDS) {
        float* sS = sPool;                  // [dl][f] stride 68 (32x68)
        const int s = bid;
        if (tid < 32) sCpS[tid] = gCp[s * 32 + tid];

        // reduce 16 split-K partials (float4)
        const float4* mp4 = reinterpret_cast<const float4*>(gMpart);
#pragma unroll
        for (int i = 0; i < 2; i++) {
            int e4 = i * 256 + tid;          // 0..511 (512 float4 = 32x16)
            int dl = e4 >> 4, fq = e4 & 15;
            size_t off = (size_t)(s * 32 + dl) * 16 + fq;
            float4 acc = make_float4(0.f, 0.f, 0.f, 0.f);
#pragma unroll
            for (int sl = 0; sl < NSL; sl++) {
                float4 v = mp4[(size_t)sl * (DD * 16) + off];
                acc.x += v.x; acc.y += v.y; acc.z += v.z; acc.w += v.w;
            }
            *reinterpret_cast<float4*>(sS + dl * 68 + fq * 4) = acc;
        }
        __syncthreads();

        // write M transposed: gMt[f*512 + s*32 + dl]
#pragma unroll
        for (int i = 0; i < 8; i++) {
            int e = i * 256 + tid;          // 0..2047
            int f = e >> 5, dl = e & 31;
            gMt[(size_t)f * DD + s * 32 + dl] = sS[dl * 68 + f];
        }

        // uPart / mbarPart over 32 rows
        {
            const int f = tid & 63, q = tid >> 6;
            float accU = 0.f, accM = 0.f;
#pragma unroll
            for (int i = 0; i < 8; i++) {
                int dl = q * 8 + i;
                float m = sS[dl * 68 + f];
                accU += sCpS[dl] * m;
                accM += m;
            }
            sR1[q * 64 + f] = accU;
            sR2[q * 64 + f] = accM;
        }
        __syncthreads();
        if (tid < 64) {
            gUpart[s * 64 + tid]    = sR1[tid] + sR1[64 + tid] + sR1[128 + tid] + sR1[192 + tid];
            gMbarpart[s * 64 + tid] = sR2[tid] + sR2[64 + tid] + sR2[128 + tid] + sR2[192 + tid];
        }

        // Apart[s] = sS^T sS (over 32 d-rows)
        const int tx = tid & 15, ty = tid >> 4;
        float acc[4][4];
#pragma unroll
        for (int i = 0; i < 4; i++)
#pragma unroll
            for (int j = 0; j < 4; j++) acc[i][j] = 0.f;
#pragma unroll 8
        for (int d = 0; d < 32; d++) {
            float4 a4 = *reinterpret_cast<const float4*>(sS + d * 68 + ty * 4);
            float4 b4 = *reinterpret_cast<const float4*>(sS + d * 68 + tx * 4);
            acc[0][0] += a4.x * b4.x; acc[0][1] += a4.x * b4.y; acc[0][2] += a4.x * b4.z; acc[0][3] += a4.x * b4.w;
            acc[1][0] += a4.y * b4.x; acc[1][1] += a4.y * b4.y; acc[1][2] += a4.y * b4.z; acc[1][3] += a4.y * b4.w;
            acc[2][0] += a4.z * b4.x; acc[2][1] += a4.z * b4.y; acc[2][2] += a4.z * b4.z; acc[2][3] += a4.z * b4.w;
            acc[3][0] += a4.w * b4.x; acc[3][1] += a4.w * b4.y; acc[3][2] += a4.w * b4.z; acc[3][3] += a4.w * b4.w;
        }
        float* outp = gApart + (size_t)s * (FF * FF) + (size_t)(ty * 4) * FF + tx * 4;
#pragma unroll
        for (int i = 0; i < 4; i++) {
            float4 o4 = make_float4(acc[i][0], acc[i][1], acc[i][2], acc[i][3]);
            *reinterpret_cast<float4*>(outp + (size_t)i * FF) = o4;
        }
    }

    grid_bar(1);

    // ================= Phase 3: blocks 0..63 =================
    if (bid >= 64) return;
    {
        float* sA = sPool;                  // stride 65 (4160 floats)
        const int b = bid;
        const int wj = tid >> 5, lane = tid & 31;

        if (tid < 64) {
            float tu = 0.f, tm = 0.f;
#pragma unroll
            for (int s = 0; s < NDS; s++) {
                tu += gUpart[s * 64 + tid];
                tm += gMbarpart[s * 64 + tid];
            }
            sU[tid] = tu * (1.0f / DD);
            sMb[tid] = tm * (1.0f / DD);
        }
        __syncthreads();

        // reduce + center A (float4 loads)
        const float4* ap4 = reinterpret_cast<const float4*>(gApart);
#pragma unroll
        for (int i = 0; i < 4; i++) {
            int e4 = i * 256 + tid;         // 0..1023 (1024 float4 = 64x16)
            int f1 = e4 >> 4, fq = e4 & 15;
            float4 acc = make_float4(0.f, 0.f, 0.f, 0.f);
#pragma unroll
            for (int sl = 0; sl < NDS; sl++) {
                float4 v = ap4[(size_t)sl * (FF * 16) + e4];
                acc.x += v.x; acc.y += v.y; acc.z += v.z; acc.w += v.w;
            }
            const float mb1 = sMb[f1];
            sA[f1 * 65 + fq * 4 + 0] = acc.x * (1.0f / DD) - mb1 * sMb[fq * 4 + 0];
            sA[f1 * 65 + fq * 4 + 1] = acc.y * (1.0f / DD) - mb1 * sMb[fq * 4 + 1];
            sA[f1 * 65 + fq * 4 + 2] = acc.z * (1.0f / DD) - mb1 * sMb[fq * 4 + 2];
            sA[f1 * 65 + fq * 4 + 3] = acc.w * (1.0f / DD) - mb1 * sMb[fq * 4 + 3];
        }
        const float v = gV[0];
        __syncthreads();

        const float* xb = x + (size_t)b * TT * FF;
        float xacc = 0.f;
        float Sacc = 0.f;

        for (int j0 = 0; j0 < n; j0 += 8) {
            const int j = j0 + wj;
            const bool valid = (j < n);
            const int t = TT - 1 - j;
            float xa = 0.f, xb2 = 0.f;
            if (valid) {
                xa  = xb[(size_t)t * FF + lane];
                xb2 = xb[(size_t)t * FF + 32 + lane];
            }
            sxc[wj][lane] = xa;
            sxc[wj][32 + lane] = xb2;
            __syncwarp();
            float aca = 0.f, acb = 0.f;
#pragma unroll 8
            for (int f2 = 0; f2 < 64; f2++) {
                float xv = sxc[wj][f2];
                aca += sA[lane * 65 + f2] * xv;
                acb += sA[(32 + lane) * 65 + f2] * xv;
            }
            float p = xa * (aca + 2.0f * sU[lane]) + xb2 * (acb + 2.0f * sU[32 + lane]);
#pragma unroll
            for (int o = 16; o > 0; o >>= 1) p += __shfl_down_sync(0xffffffffu, p, o);
            if (lane == 0) {
                float var = p + v;
                float sc = rsqrtf(var + LN_EPS);
                float w = g * exp2f((float)j * l2omg);
                scoef[wj] = valid ? (w * sc) : 0.f;
            }
            __syncthreads();
            if (tid < 64) {
#pragma unroll
                for (int jj = 0; jj < 8; jj++) xacc += scoef[jj] * sxc[jj][tid];
            }
#pragma unroll
            for (int jj = 0; jj < 8; jj++) Sacc += scoef[jj];
            __syncthreads();
        }

        if (tid < 64) sxt[tid] = xacc;
        __syncthreads();

        const float Wsum = 1.0f - exp2f((float)TT * l2omg);
        float mdot = 0.f;
#pragma unroll 8
        for (int f = 0; f < 64; f++) mdot += sMb[f] * sxt[f];

        float* ob = out + (size_t)b * DD;
        float dot0 = 0.f, dot1 = 0.f;
#pragma unroll 8
        for (int f = 0; f < 64; f++) {
            float xf = sxt[f];
            dot0 += gMt[(size_t)f * DD + tid] * xf;
            dot1 += gMt[(size_t)f * DD + 256 + tid] * xf;
        }
        ob[tid]       = gamma[tid]       * (dot0 - mdot + gCp[tid]       * Sacc) + beta[tid]       * Wsum;
        ob[256 + tid] = gamma[256 + tid] * (dot1 - mdot + gCp[256 + tid] * Sacc) + beta[256 + tid] * Wsum;
    }
}

// ---------------------------------------------------------------------------
// Inputs: x, theta1, phi1, theta2, phi2, w1, w2, b_g, P_w, W_w, W_b, b,
//         ln_gamma, ln_beta, alpha (alpha cancels inside LayerNorm).
// ---------------------------------------------------------------------------
extern "C" void kernel_launch(void* const* d_in, const int* in_sizes, int n_in,
                              void* d_out, int out_size) {
    const float* x     = (const float*)d_in[0];
    const float* th1   = (const float*)d_in[1];
    const float* ph1   = (const float*)d_in[2];
    const float* th2   = (const float*)d_in[3];
    const float* ph2   = (const float*)d_in[4];
    const float* w1p   = (const float*)d_in[5];
    const float* w2p   = (const float*)d_in[6];
    const float* bgp   = (const float*)d_in[7];
    const float* Pw    = (const float*)d_in[8];
    const float* Ww    = (const float*)d_in[9];
    const float* Wb    = (const float*)d_in[10];
    const float* bvec  = (const float*)d_in[11];
    const float* gamma = (const float*)d_in[12];
    const float* beta  = (const float*)d_in[13];

    mega<<<GRID, 256>>>(x, th1, ph1, th2, ph2, w1p, w2p, bgp,
                        Pw, Ww, Wb, bvec, gamma, beta, (float*)d_out);
}